// round 1
// baseline (speedup 1.0000x reference)
#include <cuda_runtime.h>

// Problem constants (fixed by the reference setup_inputs)
#define BB 4
#define HH 384
#define WW 512
#define CC 64
#define CH4 (CC / 4)   // 16 float4 chunks per pixel

__global__ void __launch_bounds__(256)
warp_bilinear_kernel(const float2* __restrict__ flow,    // [B,H,W] of float2
                     const float4* __restrict__ feat,    // [B,H,W,C/4] of float4
                     const float*  __restrict__ mask,    // [H,W]
                     float4*       __restrict__ out)     // [B,H,W,C/4]
{
    const int tid = blockIdx.x * blockDim.x + threadIdx.x;
    const int total = BB * HH * WW * CH4;
    if (tid >= total) return;

    const int c4  = tid & (CH4 - 1);
    const int pix = tid >> 4;              // b*H*W + py*W + px
    const int b   = pix / (HH * WW);
    const int hw  = pix - b * (HH * WW);
    const int py  = hw / WW;
    const int px  = hw - py * WW;

    const float2 fl = flow[pix];
    const float xt = (float)px + fl.x;
    const float yt = (float)py + fl.y;

    // Faithful to reference arithmetic: (2*t/(D-1) - 1 + 1) * 0.5 * D
    const float x = (2.0f * xt / (float)(WW - 1) - 1.0f + 1.0f) * 0.5f * (float)WW;
    const float y = (2.0f * yt / (float)(HH - 1) - 1.0f + 1.0f) * 0.5f * (float)HH;

    int x0 = (int)floorf(x);
    int y0 = (int)floorf(y);
    x0 = min(max(x0, 0), WW - 1);
    y0 = min(max(y0, 0), HH - 1);
    const int x1 = min(x0 + 1, WW - 1);
    const int y1 = min(y0 + 1, HH - 1);

    const float x0f = (float)x0, x1f = (float)x1;
    const float y0f = (float)y0, y1f = (float)y1;

    const float wa = (x1f - x) * (y1f - y);
    const float wb = (x1f - x) * (y - y0f);
    const float wc = (x - x0f) * (y1f - y);
    const float wd = (x - x0f) * (y - y0f);

    const long base = (long)b * (HH * WW) * CH4;
    const float4 fa = feat[base + (long)(y0 * WW + x0) * CH4 + c4];
    const float4 fb = feat[base + (long)(y1 * WW + x0) * CH4 + c4];
    const float4 fc = feat[base + (long)(y0 * WW + x1) * CH4 + c4];
    const float4 fd = feat[base + (long)(y1 * WW + x1) * CH4 + c4];

    const float m = mask[hw];

    float4 r;
    r.x = (wa * fa.x + wb * fb.x + wc * fc.x + wd * fd.x) * m;
    r.y = (wa * fa.y + wb * fb.y + wc * fc.y + wd * fd.y) * m;
    r.z = (wa * fa.z + wb * fb.z + wc * fc.z + wd * fd.z) * m;
    r.w = (wa * fa.w + wb * fb.w + wc * fc.w + wd * fd.w) * m;

    out[tid] = r;
}

extern "C" void kernel_launch(void* const* d_in, const int* in_sizes, int n_in,
                              void* d_out, int out_size)
{
    const float2* flow = (const float2*)d_in[0];   // w: [B,H,W,2]
    const float4* feat = (const float4*)d_in[1];   // feature: [B,H,W,C]
    const float*  mask = (const float*)d_in[2];    // mask: [H,W]
    float4* out = (float4*)d_out;

    const int total = BB * HH * WW * CH4;          // 12,582,912 threads
    const int threads = 256;
    const int blocks = (total + threads - 1) / threads;
    warp_bilinear_kernel<<<blocks, threads>>>(flow, feat, mask, out);
}

// round 2
// speedup vs baseline: 1.0929x; 1.0929x over previous
#include <cuda_runtime.h>

// Problem constants (fixed by the reference setup_inputs)
#define BB 4
#define HH 384
#define WW 512
#define CC 64
#define CH4 (CC / 4)        // 16 float4 chunks per pixel
#define PIXB 32             // pixels per block
#define THREADS 256         // 32 pixels x 8 threads; each thread does 2 chunks

__global__ void __launch_bounds__(THREADS)
warp_bilinear_kernel(const float2* __restrict__ flow,    // [B,H,W] of float2
                     const float4* __restrict__ feat,    // [B,H,W,C/4] of float4
                     const float*  __restrict__ mask,    // [H,W]
                     float4*       __restrict__ out)     // [B,H,W,C/4]
{
    const int lane = threadIdx.x & 7;          // chunk group: handles lane and lane+8
    const int pi   = threadIdx.x >> 3;         // pixel within block [0,32)
    const int px   = blockIdx.x * PIXB + pi;
    const int py   = blockIdx.y;
    const int b    = blockIdx.z;

    const int hw  = py * WW + px;
    const int pix = b * (HH * WW) + hw;

    const float2 fl = __ldcs(&flow[pix]);
    const float xt = (float)px + fl.x;
    const float yt = (float)py + fl.y;

    // Faithful to reference arithmetic: (2*t/(D-1) - 1 + 1) * 0.5 * D
    const float x = (2.0f * xt / (float)(WW - 1) - 1.0f + 1.0f) * 0.5f * (float)WW;
    const float y = (2.0f * yt / (float)(HH - 1) - 1.0f + 1.0f) * 0.5f * (float)HH;

    int x0 = (int)floorf(x);
    int y0 = (int)floorf(y);
    x0 = min(max(x0, 0), WW - 1);
    y0 = min(max(y0, 0), HH - 1);
    const int x1 = min(x0 + 1, WW - 1);
    const int y1 = min(y0 + 1, HH - 1);

    const float x0f = (float)x0, x1f = (float)x1;
    const float y0f = (float)y0, y1f = (float)y1;

    const float wa = (x1f - x) * (y1f - y);
    const float wb = (x1f - x) * (y - y0f);
    const float wc = (x - x0f) * (y1f - y);
    const float wd = (x - x0f) * (y - y0f);

    const float m = mask[hw];
    const float wam = wa * m, wbm = wb * m, wcm = wc * m, wdm = wd * m;

    const int base = b * (HH * WW) * CH4;
    const float4* pa = feat + base + (y0 * WW + x0) * CH4 + lane;
    const float4* pb = feat + base + (y1 * WW + x0) * CH4 + lane;
    const float4* pc = feat + base + (y0 * WW + x1) * CH4 + lane;
    const float4* pd = feat + base + (y1 * WW + x1) * CH4 + lane;

    // Two independent chunk sets (lane, lane+8) -> 8 outstanding gathers
    const float4 fa0 = pa[0], fa1 = pa[8];
    const float4 fb0 = pb[0], fb1 = pb[8];
    const float4 fc0 = pc[0], fc1 = pc[8];
    const float4 fd0 = pd[0], fd1 = pd[8];

    float4 r0, r1;
    r0.x = wam * fa0.x + wbm * fb0.x + wcm * fc0.x + wdm * fd0.x;
    r0.y = wam * fa0.y + wbm * fb0.y + wcm * fc0.y + wdm * fd0.y;
    r0.z = wam * fa0.z + wbm * fb0.z + wcm * fc0.z + wdm * fd0.z;
    r0.w = wam * fa0.w + wbm * fb0.w + wcm * fc0.w + wdm * fd0.w;

    r1.x = wam * fa1.x + wbm * fb1.x + wcm * fc1.x + wdm * fd1.x;
    r1.y = wam * fa1.y + wbm * fb1.y + wcm * fc1.y + wdm * fd1.y;
    r1.z = wam * fa1.z + wbm * fb1.z + wcm * fc1.z + wdm * fd1.z;
    r1.w = wam * fa1.w + wbm * fb1.w + wcm * fc1.w + wdm * fd1.w;

    float4* po = out + (long)pix * CH4 + lane;
    __stcs(po + 0, r0);
    __stcs(po + 8, r1);
}

extern "C" void kernel_launch(void* const* d_in, const int* in_sizes, int n_in,
                              void* d_out, int out_size)
{
    const float2* flow = (const float2*)d_in[0];   // w: [B,H,W,2]
    const float4* feat = (const float4*)d_in[1];   // feature: [B,H,W,C]
    const float*  mask = (const float*)d_in[2];    // mask: [H,W]
    float4* out = (float4*)d_out;

    dim3 grid(WW / PIXB, HH, BB);                  // (16, 384, 4)
    warp_bilinear_kernel<<<grid, THREADS>>>(flow, feat, mask, out);
}